// round 6
// baseline (speedup 1.0000x reference)
#include <cuda_runtime.h>
#include <math_constants.h>

#define NQ      4
#define LPATCH  (14*14)
#define BATCH   128
#define LTOT    (BATCH*LPATCH)   // 25088
#define NFEAT   784
#define NHID    64

__device__ float g_feat[BATCH * NFEAT];
__device__ float g_hid[BATCH * NHID];

// ============================================================================
// Circuit: 16 threads per patch, one complex amplitude per thread.
// Amplitude index = local lane (0..15); qubit q <-> bit mask (8>>q).
// Gates exchange partner amplitudes via shfl_xor within the 16-thread group.
// ============================================================================

// Fused SU(2) U = Ry(c)Rz(b)Ry(a): u.x=cB*cosP, u.y=sB*cosQ, u.z=cB*sinP, u.w=sB*sinQ
// u00=(ux,-uy) u01=(-uz,uw) u10=(uz,uw) u11=(ux,uy)
__global__ void __launch_bounds__(256) circuit_kernel(
    const float* __restrict__ x,      // [128,1,28,28]
    const float* __restrict__ w,      // [60]
    float4* __restrict__ feat)        // [LTOT] (= [128,784] floats)
{
    __shared__ float4 um[16];         // layers 0..3 x qubits 0..3
    __shared__ float  meas[4][3];     // nz,nx,ny per qubit (layer 4 folded)

    int t = threadIdx.x;
    if (t < 16) {
        int l = t >> 2, q = t & 3;
        float a = w[l * 12 + q], b = w[l * 12 + 4 + q], c = w[l * 12 + 8 + q];
        float sP, cP, sQ, cQ, sB, cB;
        sincosf(0.5f * (a + c), &sP, &cP);
        sincosf(0.5f * (a - c), &sQ, &cQ);
        sincosf(0.5f * b,       &sB, &cB);
        um[t] = make_float4(cB * cP, sB * cQ, cB * sP, sB * sQ);
    } else if (t < 20) {
        int q = t - 16;
        float a = w[48 + q], b = w[48 + 4 + q], c = w[48 + 8 + q];
        float sa, ca, sb, cb, sc, cc;
        sincosf(a, &sa, &ca);
        sincosf(b, &sb, &cb);
        sincosf(c, &sc, &cc);
        meas[q][0] =  cc * ca - sc * cb * sa;   // nz
        meas[q][1] = -cc * sa - sc * cb * ca;   // nx (coeff of 2*Re cross term)
        meas[q][2] =  sc * sb;                  // ny (coeff of 2*Im cross term)
    }
    __syncthreads();

    int g     = blockIdx.x * 256 + t;   // grid sized exactly: LTOT*16 threads
    int patch = g >> 4;
    int local = g & 15;                 // amplitude index

    int b  = patch / LPATCH;
    int p  = patch - b * LPATCH;
    int pi = p / 14, pj = p - pi * 14;

    const float* xb = x + b * 784 + (2 * pi) * 28 + 2 * pj;
    float x0 = xb[0], x1 = xb[1], x2 = xb[28], x3 = xb[29];

    float hs0, hc0, hs1, hc1, hs2, hc2, hs3, hc3;
    sincosf(CUDART_PI_F * x0, &hs0, &hc0);
    sincosf(CUDART_PI_F * x1, &hs1, &hc1);
    sincosf(CUDART_PI_F * x2, &hs2, &hc2);
    sincosf(CUDART_PI_F * x3, &hs3, &hc3);

    // amp = prod_q (bit? sin : cos) * (-i)^popcount
    float r = (local & 8 ? hs0 : hc0) * (local & 4 ? hs1 : hc1) *
              (local & 2 ? hs2 : hc2) * (local & 1 ? hs3 : hc3);
    int k = __popc(local) & 3;
    float ax = (k == 0) ? r : (k == 2) ? -r : 0.f;
    float ay = (k == 1) ? -r : (k == 3) ? r : 0.f;

    const unsigned FULL = 0xffffffffu;

#pragma unroll
    for (int l = 0; l < 4; l++) {
        // 4 fused single-qubit gates
#pragma unroll
        for (int q = 0; q < 4; q++) {
            int m = 8 >> q;
            float4 u = um[l * 4 + q];
            float px = __shfl_xor_sync(FULL, ax, m);
            float py = __shfl_xor_sync(FULL, ay, m);
            bool bt = (local & m) != 0;
            float sy = bt ? u.y : -u.y;
            float sz = bt ? u.z : -u.z;
            float nxv = u.x * ax - sy * ay + sz * px - u.w * py;
            float nyv = u.x * ay + sy * ax + sz * py + u.w * px;
            ax = nxv; ay = nyv;
        }
        // CNOT ring: (8->4) (4->2) (2->1) (1->8); swap if control bit set
        {
            float px = __shfl_xor_sync(FULL, ax, 4);
            float py = __shfl_xor_sync(FULL, ay, 4);
            if (local & 8) { ax = px; ay = py; }
        }
        {
            float px = __shfl_xor_sync(FULL, ax, 2);
            float py = __shfl_xor_sync(FULL, ay, 2);
            if (local & 4) { ax = px; ay = py; }
        }
        {
            float px = __shfl_xor_sync(FULL, ax, 1);
            float py = __shfl_xor_sync(FULL, ay, 1);
            if (local & 2) { ax = px; ay = py; }
        }
        {
            float px = __shfl_xor_sync(FULL, ax, 8);
            float py = __shfl_xor_sync(FULL, ay, 8);
            if (local & 1) { ax = px; ay = py; }
        }
    }

    // Layer 4 folded into measurement:
    // e_q = sum_threads [ nz*(+-|a|^2) + nx*(ax*px+ay*py) + ny*(+-(ax*py-ay*px)) ]
    float pr = ax * ax + ay * ay;
    float e[4];
#pragma unroll
    for (int q = 0; q < 4; q++) {
        int m = 8 >> q;
        float px = __shfl_xor_sync(FULL, ax, m);
        float py = __shfl_xor_sync(FULL, ay, m);
        bool bt = (local & m) != 0;
        float zc = bt ? -pr : pr;
        float xc = ax * px + ay * py;
        float yc = ax * py - ay * px;
        if (bt) yc = -yc;
        e[q] = meas[q][0] * zc + meas[q][1] * xc + meas[q][2] * yc;
    }
    // reduce over the 16-thread group
#pragma unroll
    for (int off = 8; off > 0; off >>= 1) {
#pragma unroll
        for (int q = 0; q < 4; q++)
            e[q] += __shfl_xor_sync(FULL, e[q], off);
    }
    if (local == 0)
        feat[patch] = make_float4(e[0], e[1], e[2], e[3]);
}

// ============================================================================
// MLP layer 1: warp per (2 batch rows x 4 neurons) -> 1024 warps.
// ============================================================================
__global__ void __launch_bounds__(256) mlp1_kernel(
    const float* __restrict__ feat,   // [128,784]
    const float* __restrict__ w1,     // [64,784]
    const float* __restrict__ b1,     // [64]
    float* __restrict__ hid)          // [128,64]
{
    int gtid = blockIdx.x * blockDim.x + threadIdx.x;
    int warp = gtid >> 5;
    int lane = gtid & 31;
    int wb = warp >> 4;          // 0..63 batch group
    int wn = warp & 15;          // 0..15 neuron group
    int b0 = wb * 2;
    int n0 = wn * 4;

    const float4* f0 = reinterpret_cast<const float4*>(feat + (b0 + 0) * NFEAT);
    const float4* f1 = reinterpret_cast<const float4*>(feat + (b0 + 1) * NFEAT);
    const float4* wv0 = reinterpret_cast<const float4*>(w1 + (n0 + 0) * NFEAT);
    const float4* wv1 = reinterpret_cast<const float4*>(w1 + (n0 + 1) * NFEAT);
    const float4* wv2 = reinterpret_cast<const float4*>(w1 + (n0 + 2) * NFEAT);
    const float4* wv3 = reinterpret_cast<const float4*>(w1 + (n0 + 3) * NFEAT);

    float a00 = 0.f, a01 = 0.f, a02 = 0.f, a03 = 0.f;
    float a10 = 0.f, a11 = 0.f, a12 = 0.f, a13 = 0.f;
#pragma unroll
    for (int kk = lane; kk < NFEAT / 4; kk += 32) {
        float4 fa = f0[kk];
        float4 fb = f1[kk];
        float4 w0 = wv0[kk], w1v = wv1[kk], w2v = wv2[kk], w3v = wv3[kk];
        a00 = fmaf(fa.x, w0.x,  fmaf(fa.y, w0.y,  fmaf(fa.z, w0.z,  fmaf(fa.w, w0.w,  a00))));
        a01 = fmaf(fa.x, w1v.x, fmaf(fa.y, w1v.y, fmaf(fa.z, w1v.z, fmaf(fa.w, w1v.w, a01))));
        a02 = fmaf(fa.x, w2v.x, fmaf(fa.y, w2v.y, fmaf(fa.z, w2v.z, fmaf(fa.w, w2v.w, a02))));
        a03 = fmaf(fa.x, w3v.x, fmaf(fa.y, w3v.y, fmaf(fa.z, w3v.z, fmaf(fa.w, w3v.w, a03))));
        a10 = fmaf(fb.x, w0.x,  fmaf(fb.y, w0.y,  fmaf(fb.z, w0.z,  fmaf(fb.w, w0.w,  a10))));
        a11 = fmaf(fb.x, w1v.x, fmaf(fb.y, w1v.y, fmaf(fb.z, w1v.z, fmaf(fb.w, w1v.w, a11))));
        a12 = fmaf(fb.x, w2v.x, fmaf(fb.y, w2v.y, fmaf(fb.z, w2v.z, fmaf(fb.w, w2v.w, a12))));
        a13 = fmaf(fb.x, w3v.x, fmaf(fb.y, w3v.y, fmaf(fb.z, w3v.z, fmaf(fb.w, w3v.w, a13))));
    }
#pragma unroll
    for (int off = 16; off > 0; off >>= 1) {
        a00 += __shfl_xor_sync(0xffffffffu, a00, off);
        a01 += __shfl_xor_sync(0xffffffffu, a01, off);
        a02 += __shfl_xor_sync(0xffffffffu, a02, off);
        a03 += __shfl_xor_sync(0xffffffffu, a03, off);
        a10 += __shfl_xor_sync(0xffffffffu, a10, off);
        a11 += __shfl_xor_sync(0xffffffffu, a11, off);
        a12 += __shfl_xor_sync(0xffffffffu, a12, off);
        a13 += __shfl_xor_sync(0xffffffffu, a13, off);
    }
    if (lane == 0) {
        float bb0 = b1[n0], bb1 = b1[n0 + 1], bb2 = b1[n0 + 2], bb3 = b1[n0 + 3];
        float* h0 = hid + (b0 + 0) * NHID + n0;
        float* h1 = hid + (b0 + 1) * NHID + n0;
        h0[0] = fmaxf(a00 + bb0, 0.f); h0[1] = fmaxf(a01 + bb1, 0.f);
        h0[2] = fmaxf(a02 + bb2, 0.f); h0[3] = fmaxf(a03 + bb3, 0.f);
        h1[0] = fmaxf(a10 + bb0, 0.f); h1[1] = fmaxf(a11 + bb1, 0.f);
        h1[2] = fmaxf(a12 + bb2, 0.f); h1[3] = fmaxf(a13 + bb3, 0.f);
    }
}

// ============================================================================
// MLP layer 2: warp per (batch row, output). 1280 warps.
// ============================================================================
__global__ void __launch_bounds__(256) mlp2_kernel(
    const float* __restrict__ hid,    // [128,64]
    const float* __restrict__ w2,     // [10,64]
    const float* __restrict__ b2,     // [10]
    float* __restrict__ out)          // [128,10]
{
    int gtid = blockIdx.x * blockDim.x + threadIdx.x;
    int warp = gtid >> 5;
    int lane = gtid & 31;
    if (warp >= BATCH * 10) return;
    int b = warp / 10;
    int o = warp - b * 10;

    float acc = 0.f;
    if (lane < 16) {
        const float4* hv = reinterpret_cast<const float4*>(hid + b * NHID);
        const float4* wv = reinterpret_cast<const float4*>(w2 + o * NHID);
        float4 h = hv[lane];
        float4 ww = wv[lane];
        acc = h.x * ww.x + h.y * ww.y + h.z * ww.z + h.w * ww.w;
    }
#pragma unroll
    for (int off = 8; off > 0; off >>= 1)
        acc += __shfl_xor_sync(0xffffffffu, acc, off);

    if (lane == 0)
        out[b * 10 + o] = acc + b2[o];
}

extern "C" void kernel_launch(void* const* d_in, const int* in_sizes, int n_in,
                              void* d_out, int out_size) {
    const float* x     = (const float*)d_in[0];
    const float* w     = (const float*)d_in[1];
    const float* fc1_w = (const float*)d_in[2];
    const float* fc1_b = (const float*)d_in[3];
    const float* fc2_w = (const float*)d_in[4];
    const float* fc2_b = (const float*)d_in[5];
    float* out = (float*)d_out;

    // LTOT*16 = 401408 threads = 1568 blocks of 256 (exact, no tail)
    circuit_kernel<<<LTOT * 16 / 256, 256>>>(x, w, (float4*)g_feat);
    // 1024 warps = 128 blocks of 256
    mlp1_kernel<<<128, 256>>>(g_feat, fc1_w, fc1_b, g_hid);
    // 1280 warps = 160 blocks of 256
    mlp2_kernel<<<160, 256>>>(g_hid, fc2_w, fc2_b, out);
}

// round 7
// speedup vs baseline: 1.2877x; 1.2877x over previous
#include <cuda_runtime.h>
#include <math_constants.h>

#define NQ      4
#define LPATCH  (14*14)
#define BATCH   128
#define LTOT    (BATCH*LPATCH)   // 25088
#define NFEAT   784
#define NHID    64

__device__ float g_feat[BATCH * NFEAT];

// ============================================================================
// Circuit: 4 threads per patch, 4 amplitudes per thread.
// Amp index i (0..15): q0=i&8, q1=i&4, q2=i&2, q3=i&1.
// Thread s = i>>2 (s&2 = q0, s&1 = q1);  register r = i&3 (r&2 = q2, r&1 = q3).
// Fused SU(2) U = Ry(c)Rz(b)Ry(a): u.x=cB*cosP, u.y=sB*cosQ, u.z=cB*sinP, u.w=sB*sinQ
// u00=(ux,-uy) u01=(-uz,uw) u10=(uz,uw) u11=(ux,uy)
// ============================================================================

// Full complex 2x2 on an in-register pair (lo, hi)
#define LOCAL_GATE(u, lox, loy, hix, hiy) do {                        \
    float _lx = (u).x*(lox) + (u).y*(loy) - (u).z*(hix) - (u).w*(hiy);\
    float _ly = (u).x*(loy) - (u).y*(lox) - (u).z*(hiy) + (u).w*(hix);\
    float _hx = (u).z*(lox) - (u).w*(loy) + (u).x*(hix) - (u).y*(hiy);\
    float _hy = (u).z*(loy) + (u).w*(lox) + (u).x*(hiy) + (u).y*(hix);\
    (lox)=_lx; (loy)=_ly; (hix)=_hx; (hiy)=_hy;                       \
} while (0)

__global__ void __launch_bounds__(256) circuit_kernel(
    const float* __restrict__ x,      // [128,1,28,28]
    const float* __restrict__ w,      // [60]
    float4* __restrict__ feat)        // [LTOT] float4 (= [128,784] floats)
{
    __shared__ float4 um[16];         // layers 0..3 x qubits 0..3
    __shared__ float  meas[4][3];     // nz,nx,ny per qubit (layer 4 folded)

    int t = threadIdx.x;
    if (t < 16) {
        int l = t >> 2, q = t & 3;
        float a = w[l * 12 + q], b = w[l * 12 + 4 + q], c = w[l * 12 + 8 + q];
        float sP, cP, sQ, cQ, sB, cB;
        sincosf(0.5f * (a + c), &sP, &cP);
        sincosf(0.5f * (a - c), &sQ, &cQ);
        sincosf(0.5f * b,       &sB, &cB);
        um[t] = make_float4(cB * cP, sB * cQ, cB * sP, sB * sQ);
    } else if (t < 20) {
        int q = t - 16;
        float a = w[48 + q], b = w[48 + 4 + q], c = w[48 + 8 + q];
        float sa, ca, sb, cb, sc, cc;
        sincosf(a, &sa, &ca);
        sincosf(b, &sb, &cb);
        sincosf(c, &sc, &cc);
        meas[q][0] =  cc * ca - sc * cb * sa;   // nz
        meas[q][1] = -cc * sa - sc * cb * ca;   // nx
        meas[q][2] =  sc * sb;                  // ny
    }
    __syncthreads();

    const unsigned FULL = 0xffffffffu;
    int g     = blockIdx.x * 256 + t;   // grid exact: LTOT*4 threads
    int patch = g >> 2;
    int s     = g & 3;
    int lane  = t & 31;

    int b  = patch / LPATCH;
    int p  = patch - b * LPATCH;
    int pi = p / 14, pj = p - pi * 14;

    // thread s computes sincos of its own pixel, then broadcast all 4
    const float* xb = x + b * 784 + (2 * pi) * 28 + 2 * pj;
    float xpix = xb[(s >> 1) * 28 + (s & 1)];
    float hs_l, hc_l;
    __sincosf(CUDART_PI_F * xpix, &hs_l, &hc_l);

    int base = lane & ~3;
    float hcq[4], hsq[4];
#pragma unroll
    for (int q = 0; q < 4; q++) {
        hcq[q] = __shfl_sync(FULL, hc_l, base + q);
        hsq[q] = __shfl_sync(FULL, hs_l, base + q);
    }

    // init: amp = prod_q (bit? sin : cos) * (-i)^popc
    float f01 = (s & 2 ? hsq[0] : hcq[0]) * (s & 1 ? hsq[1] : hcq[1]);
    int pcs = __popc(s);
    float ax[4], ay[4];
#pragma unroll
    for (int r = 0; r < 4; r++) {
        float mag = f01 * (r & 2 ? hsq[2] : hcq[2]) * (r & 1 ? hsq[3] : hcq[3]);
        int k = (pcs + __popc(r)) & 3;
        ax[r] = (k == 0) ? mag : (k == 2) ? -mag : 0.f;
        ay[r] = (k == 1) ? -mag : (k == 3) ? mag : 0.f;
    }

#pragma unroll
    for (int l = 0; l < 4; l++) {
        // gate on q0 (thread bit 2, shfl mask 2)
        {
            float4 u = um[l * 4 + 0];
            bool bt = (s & 2) != 0;
            float sy = bt ? u.y : -u.y;
            float sz = bt ? u.z : -u.z;
#pragma unroll
            for (int r = 0; r < 4; r++) {
                float px = __shfl_xor_sync(FULL, ax[r], 2);
                float py = __shfl_xor_sync(FULL, ay[r], 2);
                float nx_ = u.x * ax[r] - sy * ay[r] + sz * px - u.w * py;
                float ny_ = u.x * ay[r] + sy * ax[r] + sz * py + u.w * px;
                ax[r] = nx_; ay[r] = ny_;
            }
        }
        // gate on q1 (thread bit 1, shfl mask 1)
        {
            float4 u = um[l * 4 + 1];
            bool bt = (s & 1) != 0;
            float sy = bt ? u.y : -u.y;
            float sz = bt ? u.z : -u.z;
#pragma unroll
            for (int r = 0; r < 4; r++) {
                float px = __shfl_xor_sync(FULL, ax[r], 1);
                float py = __shfl_xor_sync(FULL, ay[r], 1);
                float nx_ = u.x * ax[r] - sy * ay[r] + sz * px - u.w * py;
                float ny_ = u.x * ay[r] + sy * ax[r] + sz * py + u.w * px;
                ax[r] = nx_; ay[r] = ny_;
            }
        }
        // gate on q2 (register bit 1): pairs (0,2),(1,3)
        {
            float4 u = um[l * 4 + 2];
            LOCAL_GATE(u, ax[0], ay[0], ax[2], ay[2]);
            LOCAL_GATE(u, ax[1], ay[1], ax[3], ay[3]);
        }
        // gate on q3 (register bit 0): pairs (0,1),(2,3)
        {
            float4 u = um[l * 4 + 3];
            LOCAL_GATE(u, ax[0], ay[0], ax[1], ay[1]);
            LOCAL_GATE(u, ax[2], ay[2], ax[3], ay[3]);
        }
        // CNOT(q0->q1): threads with s&2 exchange all amps with lane^1
#pragma unroll
        for (int r = 0; r < 4; r++) {
            float px = __shfl_xor_sync(FULL, ax[r], 1);
            float py = __shfl_xor_sync(FULL, ay[r], 1);
            if (s & 2) { ax[r] = px; ay[r] = py; }
        }
        // CNOT(q1->q2): if s&1, swap (0<->2),(1<->3)
        if (s & 1) {
            float tx;
            tx = ax[0]; ax[0] = ax[2]; ax[2] = tx;
            tx = ay[0]; ay[0] = ay[2]; ay[2] = tx;
            tx = ax[1]; ax[1] = ax[3]; ax[3] = tx;
            tx = ay[1]; ay[1] = ay[3]; ay[3] = tx;
        }
        // CNOT(q2->q3): swap a2<->a3 (pure register rename)
        {
            float tx;
            tx = ax[2]; ax[2] = ax[3]; ax[3] = tx;
            tx = ay[2]; ay[2] = ay[3]; ay[3] = tx;
        }
        // CNOT(q3->q0): amps r=1,3 exchange across lane^2 (unconditional)
        ax[1] = __shfl_xor_sync(FULL, ax[1], 2);
        ay[1] = __shfl_xor_sync(FULL, ay[1], 2);
        ax[3] = __shfl_xor_sync(FULL, ax[3], 2);
        ay[3] = __shfl_xor_sync(FULL, ay[3], 2);
    }

    // Layer 4 folded into measurement: e_q = nz*<Z> + nx*<X> + ny*<Y>
    float pr[4];
#pragma unroll
    for (int r = 0; r < 4; r++) pr[r] = ax[r] * ax[r] + ay[r] * ay[r];

    float e0, e1, e2, e3;
    // q0 (cross, mask 2)
    {
        float zc = 0.f, xc = 0.f, yc = 0.f;
#pragma unroll
        for (int r = 0; r < 4; r++) {
            float px = __shfl_xor_sync(FULL, ax[r], 2);
            float py = __shfl_xor_sync(FULL, ay[r], 2);
            zc += pr[r];
            xc += ax[r] * px + ay[r] * py;
            yc += ax[r] * py - ay[r] * px;
        }
        if (s & 2) { zc = -zc; yc = -yc; }
        e0 = meas[0][0] * zc + meas[0][1] * xc + meas[0][2] * yc;
    }
    // q1 (cross, mask 1)
    {
        float zc = 0.f, xc = 0.f, yc = 0.f;
#pragma unroll
        for (int r = 0; r < 4; r++) {
            float px = __shfl_xor_sync(FULL, ax[r], 1);
            float py = __shfl_xor_sync(FULL, ay[r], 1);
            zc += pr[r];
            xc += ax[r] * px + ay[r] * py;
            yc += ax[r] * py - ay[r] * px;
        }
        if (s & 1) { zc = -zc; yc = -yc; }
        e1 = meas[1][0] * zc + meas[1][1] * xc + meas[1][2] * yc;
    }
    // q2 (local): pairs (0,2),(1,3)
    {
        float zc = pr[0] + pr[1] - pr[2] - pr[3];
        float xc = 2.f * (ax[0] * ax[2] + ay[0] * ay[2] + ax[1] * ax[3] + ay[1] * ay[3]);
        float yc = 2.f * (ax[0] * ay[2] - ay[0] * ax[2] + ax[1] * ay[3] - ay[1] * ax[3]);
        e2 = meas[2][0] * zc + meas[2][1] * xc + meas[2][2] * yc;
    }
    // q3 (local): pairs (0,1),(2,3)
    {
        float zc = pr[0] - pr[1] + pr[2] - pr[3];
        float xc = 2.f * (ax[0] * ax[1] + ay[0] * ay[1] + ax[2] * ax[3] + ay[2] * ay[3]);
        float yc = 2.f * (ax[0] * ay[1] - ay[0] * ax[1] + ax[2] * ay[3] - ay[2] * ax[3]);
        e3 = meas[3][0] * zc + meas[3][1] * xc + meas[3][2] * yc;
    }
    // reduce over the 4-thread group
    e0 += __shfl_xor_sync(FULL, e0, 1);
    e1 += __shfl_xor_sync(FULL, e1, 1);
    e2 += __shfl_xor_sync(FULL, e2, 1);
    e3 += __shfl_xor_sync(FULL, e3, 1);
    e0 += __shfl_xor_sync(FULL, e0, 2);
    e1 += __shfl_xor_sync(FULL, e1, 2);
    e2 += __shfl_xor_sync(FULL, e2, 2);
    e3 += __shfl_xor_sync(FULL, e3, 2);

    if (s == 0)
        feat[patch] = make_float4(e0, e1, e2, e3);
}

// ============================================================================
// Fused MLP: one block (512 thr) per batch row.
// Stage A: 16 warps x 4 neurons -> hid in smem. Stage B: warps 0..9 -> out.
// ============================================================================
__global__ void __launch_bounds__(512) mlp_kernel(
    const float* __restrict__ feat,   // [128,784]
    const float* __restrict__ w1,     // [64,784]
    const float* __restrict__ b1,     // [64]
    const float* __restrict__ w2,     // [10,64]
    const float* __restrict__ b2,     // [10]
    float* __restrict__ out)          // [128,10]
{
    __shared__ float4 hid4[NHID / 4];
    int b = blockIdx.x;
    int t = threadIdx.x;
    int warp = t >> 5, lane = t & 31;
    int n0 = warp * 4;

    const float4* fv  = reinterpret_cast<const float4*>(feat + b * NFEAT);
    const float4* wv0 = reinterpret_cast<const float4*>(w1 + (n0 + 0) * NFEAT);
    const float4* wv1 = reinterpret_cast<const float4*>(w1 + (n0 + 1) * NFEAT);
    const float4* wv2 = reinterpret_cast<const float4*>(w1 + (n0 + 2) * NFEAT);
    const float4* wv3 = reinterpret_cast<const float4*>(w1 + (n0 + 3) * NFEAT);

    float a0 = 0.f, a1 = 0.f, a2 = 0.f, a3 = 0.f;
    if (lane < 28) {
        // 196 float4 = 7 iters x 28 lanes, fully unrolled, coalesced
#pragma unroll
        for (int j = 0; j < 7; j++) {
            int k = j * 28 + lane;
            float4 fa = fv[k];
            float4 w0 = wv0[k], w1v = wv1[k], w2v = wv2[k], w3v = wv3[k];
            a0 = fmaf(fa.x, w0.x,  fmaf(fa.y, w0.y,  fmaf(fa.z, w0.z,  fmaf(fa.w, w0.w,  a0))));
            a1 = fmaf(fa.x, w1v.x, fmaf(fa.y, w1v.y, fmaf(fa.z, w1v.z, fmaf(fa.w, w1v.w, a1))));
            a2 = fmaf(fa.x, w2v.x, fmaf(fa.y, w2v.y, fmaf(fa.z, w2v.z, fmaf(fa.w, w2v.w, a2))));
            a3 = fmaf(fa.x, w3v.x, fmaf(fa.y, w3v.y, fmaf(fa.z, w3v.z, fmaf(fa.w, w3v.w, a3))));
        }
    }
#pragma unroll
    for (int off = 16; off > 0; off >>= 1) {
        a0 += __shfl_xor_sync(0xffffffffu, a0, off);
        a1 += __shfl_xor_sync(0xffffffffu, a1, off);
        a2 += __shfl_xor_sync(0xffffffffu, a2, off);
        a3 += __shfl_xor_sync(0xffffffffu, a3, off);
    }
    if (lane == 0) {
        float* hs = reinterpret_cast<float*>(hid4);
        hs[n0 + 0] = fmaxf(a0 + b1[n0 + 0], 0.f);
        hs[n0 + 1] = fmaxf(a1 + b1[n0 + 1], 0.f);
        hs[n0 + 2] = fmaxf(a2 + b1[n0 + 2], 0.f);
        hs[n0 + 3] = fmaxf(a3 + b1[n0 + 3], 0.f);
    }
    __syncthreads();

    // Stage B: 10 warps, one output each
    if (warp < 10) {
        float acc = 0.f;
        if (lane < 16) {
            float4 h  = hid4[lane];
            float4 ww = reinterpret_cast<const float4*>(w2 + warp * NHID)[lane];
            acc = h.x * ww.x + h.y * ww.y + h.z * ww.z + h.w * ww.w;
        }
#pragma unroll
        for (int off = 8; off > 0; off >>= 1)
            acc += __shfl_xor_sync(0xffffffffu, acc, off);
        if (lane == 0)
            out[b * 10 + warp] = acc + b2[warp];
    }
}

extern "C" void kernel_launch(void* const* d_in, const int* in_sizes, int n_in,
                              void* d_out, int out_size) {
    const float* x     = (const float*)d_in[0];
    const float* w     = (const float*)d_in[1];
    const float* fc1_w = (const float*)d_in[2];
    const float* fc1_b = (const float*)d_in[3];
    const float* fc2_w = (const float*)d_in[4];
    const float* fc2_b = (const float*)d_in[5];
    float* out = (float*)d_out;

    // LTOT*4 = 100352 threads = 392 blocks of 256 (exact)
    circuit_kernel<<<LTOT * 4 / 256, 256>>>(x, w, (float4*)g_feat);
    mlp_kernel<<<BATCH, 512>>>(g_feat, fc1_w, fc1_b, fc2_w, fc2_b, out);
}

// round 8
// speedup vs baseline: 1.8114x; 1.4068x over previous
#include <cuda_runtime.h>
#include <math_constants.h>

#define LPATCH  (14*14)
#define BATCH   128
#define NFEAT   784
#define NHID    64

// Dynamic smem layout (bytes)
#define FEAT_OFF 0               // 196 float4 = 3136 B
#define W1_OFF   3136            // 64*784 floats = 200704 B
#define W2_OFF   203840          // 10*64 floats = 2560 B
#define B1_OFF   206400          // 64 floats = 256 B
#define HID_OFF  206656          // 64 floats = 256 B
#define SMEM_TOTAL 206912

__device__ __forceinline__ void cp_async16(void* sptr, const void* gptr) {
    unsigned s = (unsigned)__cvta_generic_to_shared(sptr);
    asm volatile("cp.async.cg.shared.global [%0], [%1], 16;\n" :: "r"(s), "l"(gptr));
}

// Full complex 2x2 on an in-register amplitude pair
#define LOCAL_GATE(u, lox, loy, hix, hiy) do {                        \
    float _lx = (u).x*(lox) + (u).y*(loy) - (u).z*(hix) - (u).w*(hiy);\
    float _ly = (u).x*(loy) - (u).y*(lox) - (u).z*(hiy) + (u).w*(hix);\
    float _hx = (u).z*(lox) - (u).w*(loy) + (u).x*(hix) - (u).y*(hiy);\
    float _hy = (u).z*(loy) + (u).w*(lox) + (u).x*(hiy) + (u).y*(hix);\
    (lox)=_lx; (loy)=_ly; (hix)=_hx; (hiy)=_hy;                       \
} while (0)

// One block per batch row: 832 threads.
//   threads 0..783 : circuit, 4 threads per patch (196 patches), feat -> smem
//   all threads    : cp.async prefetch of w1/w2/b1 into smem (hidden behind circuit)
//   warps 0..15    : fc1 (4 neurons each) from smem
//   warps 0..9     : fc2 -> out
__global__ void __launch_bounds__(832, 1) fused_kernel(
    const float* __restrict__ x,      // [128,1,28,28]
    const float* __restrict__ w,      // [60]
    const float* __restrict__ w1,     // [64,784]
    const float* __restrict__ b1,     // [64]
    const float* __restrict__ w2,     // [10,64]
    const float* __restrict__ b2,     // [10]
    float* __restrict__ out)          // [128,10]
{
    extern __shared__ char smem_raw[];
    float4* feat4 = reinterpret_cast<float4*>(smem_raw + FEAT_OFF);
    float*  w1s   = reinterpret_cast<float*>(smem_raw + W1_OFF);
    float*  w2s   = reinterpret_cast<float*>(smem_raw + W2_OFF);
    float*  b1s   = reinterpret_cast<float*>(smem_raw + B1_OFF);
    float*  hids  = reinterpret_cast<float*>(smem_raw + HID_OFF);

    __shared__ float4 um[16];         // fused yzy, layers 0..3 x qubits 0..3
    __shared__ float  meas[4][3];     // nz,nx,ny per qubit (layer 4 folded)

    const int t = threadIdx.x;
    const int b = blockIdx.x;

    // ---- 1. fire-and-forget prefetch of MLP weights into smem ----
    for (int i = t; i < (NHID * NFEAT) / 4; i += 832)      // 12544 16B chunks
        cp_async16(w1s + i * 4, w1 + i * 4);
    if (t < 160) cp_async16(w2s + t * 4, w2 + t * 4);      // 2560 B
    if (t < 16)  cp_async16(b1s + t * 4, b1 + t * 4);      // 256 B
    asm volatile("cp.async.commit_group;\n" ::: "memory");

    // ---- 2. gate-constant setup ----
    if (t < 16) {
        int l = t >> 2, q = t & 3;
        float a = w[l * 12 + q], bb = w[l * 12 + 4 + q], c = w[l * 12 + 8 + q];
        float sP, cP, sQ, cQ, sB, cB;
        sincosf(0.5f * (a + c), &sP, &cP);
        sincosf(0.5f * (a - c), &sQ, &cQ);
        sincosf(0.5f * bb,      &sB, &cB);
        um[t] = make_float4(cB * cP, sB * cQ, cB * sP, sB * sQ);
    } else if (t < 20) {
        int q = t - 16;
        float a = w[48 + q], bb = w[48 + 4 + q], c = w[48 + 8 + q];
        float sa, ca, sb, cb, sc, cc;
        sincosf(a, &sa, &ca);
        sincosf(bb, &sb, &cb);
        sincosf(c, &sc, &cc);
        meas[q][0] =  cc * ca - sc * cb * sa;   // nz
        meas[q][1] = -cc * sa - sc * cb * ca;   // nx
        meas[q][2] =  sc * sb;                  // ny
    }
    __syncthreads();

    const unsigned FULL = 0xffffffffu;
    const int lane = t & 31;
    const int warp = t >> 5;

    // ---- 3. circuit: threads 0..799 (warps 0..24); groups of 4 = one patch ----
    if (t < 800) {
        int p = t >> 2;
        if (p > 195) p = 195;           // dummy lanes in warp 24 (no write)
        const int s = t & 3;
        const int pi = p / 14, pj = p - pi * 14;

        const float* xb = x + b * 784 + (2 * pi) * 28 + 2 * pj;
        float xpix = xb[(s >> 1) * 28 + (s & 1)];
        float hs_l, hc_l;
        __sincosf(CUDART_PI_F * xpix, &hs_l, &hc_l);

        int base = lane & ~3;
        float hcq[4], hsq[4];
#pragma unroll
        for (int q = 0; q < 4; q++) {
            hcq[q] = __shfl_sync(FULL, hc_l, base + q);
            hsq[q] = __shfl_sync(FULL, hs_l, base + q);
        }

        float f01 = (s & 2 ? hsq[0] : hcq[0]) * (s & 1 ? hsq[1] : hcq[1]);
        int pcs = __popc(s);
        float ax[4], ay[4];
#pragma unroll
        for (int r = 0; r < 4; r++) {
            float mag = f01 * (r & 2 ? hsq[2] : hcq[2]) * (r & 1 ? hsq[3] : hcq[3]);
            int k = (pcs + __popc(r)) & 3;
            ax[r] = (k == 0) ? mag : (k == 2) ? -mag : 0.f;
            ay[r] = (k == 1) ? -mag : (k == 3) ? mag : 0.f;
        }

#pragma unroll
        for (int l = 0; l < 4; l++) {
            {   // gate q0 (thread bit 2)
                float4 u = um[l * 4 + 0];
                bool bt = (s & 2) != 0;
                float sy = bt ? u.y : -u.y;
                float sz = bt ? u.z : -u.z;
#pragma unroll
                for (int r = 0; r < 4; r++) {
                    float px = __shfl_xor_sync(FULL, ax[r], 2);
                    float py = __shfl_xor_sync(FULL, ay[r], 2);
                    float nx_ = u.x * ax[r] - sy * ay[r] + sz * px - u.w * py;
                    float ny_ = u.x * ay[r] + sy * ax[r] + sz * py + u.w * px;
                    ax[r] = nx_; ay[r] = ny_;
                }
            }
            {   // gate q1 (thread bit 1)
                float4 u = um[l * 4 + 1];
                bool bt = (s & 1) != 0;
                float sy = bt ? u.y : -u.y;
                float sz = bt ? u.z : -u.z;
#pragma unroll
                for (int r = 0; r < 4; r++) {
                    float px = __shfl_xor_sync(FULL, ax[r], 1);
                    float py = __shfl_xor_sync(FULL, ay[r], 1);
                    float nx_ = u.x * ax[r] - sy * ay[r] + sz * px - u.w * py;
                    float ny_ = u.x * ay[r] + sy * ax[r] + sz * py + u.w * px;
                    ax[r] = nx_; ay[r] = ny_;
                }
            }
            {   // gate q2 (register bit 1)
                float4 u = um[l * 4 + 2];
                LOCAL_GATE(u, ax[0], ay[0], ax[2], ay[2]);
                LOCAL_GATE(u, ax[1], ay[1], ax[3], ay[3]);
            }
            {   // gate q3 (register bit 0)
                float4 u = um[l * 4 + 3];
                LOCAL_GATE(u, ax[0], ay[0], ax[1], ay[1]);
                LOCAL_GATE(u, ax[2], ay[2], ax[3], ay[3]);
            }
            // CNOT(q0->q1)
#pragma unroll
            for (int r = 0; r < 4; r++) {
                float px = __shfl_xor_sync(FULL, ax[r], 1);
                float py = __shfl_xor_sync(FULL, ay[r], 1);
                if (s & 2) { ax[r] = px; ay[r] = py; }
            }
            // CNOT(q1->q2)
            if (s & 1) {
                float tx;
                tx = ax[0]; ax[0] = ax[2]; ax[2] = tx;
                tx = ay[0]; ay[0] = ay[2]; ay[2] = tx;
                tx = ax[1]; ax[1] = ax[3]; ax[3] = tx;
                tx = ay[1]; ay[1] = ay[3]; ay[3] = tx;
            }
            // CNOT(q2->q3): register rename
            {
                float tx;
                tx = ax[2]; ax[2] = ax[3]; ax[3] = tx;
                tx = ay[2]; ay[2] = ay[3]; ay[3] = tx;
            }
            // CNOT(q3->q0)
            ax[1] = __shfl_xor_sync(FULL, ax[1], 2);
            ay[1] = __shfl_xor_sync(FULL, ay[1], 2);
            ax[3] = __shfl_xor_sync(FULL, ax[3], 2);
            ay[3] = __shfl_xor_sync(FULL, ay[3], 2);
        }

        // layer-4-folded measurement
        float pr[4];
#pragma unroll
        for (int r = 0; r < 4; r++) pr[r] = ax[r] * ax[r] + ay[r] * ay[r];

        float e0, e1, e2, e3;
        {   // q0 (cross, mask 2)
            float zc = 0.f, xc = 0.f, yc = 0.f;
#pragma unroll
            for (int r = 0; r < 4; r++) {
                float px = __shfl_xor_sync(FULL, ax[r], 2);
                float py = __shfl_xor_sync(FULL, ay[r], 2);
                zc += pr[r];
                xc += ax[r] * px + ay[r] * py;
                yc += ax[r] * py - ay[r] * px;
            }
            if (s & 2) { zc = -zc; yc = -yc; }
            e0 = meas[0][0] * zc + meas[0][1] * xc + meas[0][2] * yc;
        }
        {   // q1 (cross, mask 1)
            float zc = 0.f, xc = 0.f, yc = 0.f;
#pragma unroll
            for (int r = 0; r < 4; r++) {
                float px = __shfl_xor_sync(FULL, ax[r], 1);
                float py = __shfl_xor_sync(FULL, ay[r], 1);
                zc += pr[r];
                xc += ax[r] * px + ay[r] * py;
                yc += ax[r] * py - ay[r] * px;
            }
            if (s & 1) { zc = -zc; yc = -yc; }
            e1 = meas[1][0] * zc + meas[1][1] * xc + meas[1][2] * yc;
        }
        {   // q2 (local)
            float zc = pr[0] + pr[1] - pr[2] - pr[3];
            float xc = 2.f * (ax[0]*ax[2] + ay[0]*ay[2] + ax[1]*ax[3] + ay[1]*ay[3]);
            float yc = 2.f * (ax[0]*ay[2] - ay[0]*ax[2] + ax[1]*ay[3] - ay[1]*ax[3]);
            e2 = meas[2][0] * zc + meas[2][1] * xc + meas[2][2] * yc;
        }
        {   // q3 (local)
            float zc = pr[0] - pr[1] + pr[2] - pr[3];
            float xc = 2.f * (ax[0]*ax[1] + ay[0]*ay[1] + ax[2]*ax[3] + ay[2]*ay[3]);
            float yc = 2.f * (ax[0]*ay[1] - ay[0]*ax[1] + ax[2]*ay[3] - ay[2]*ax[3]);
            e3 = meas[3][0] * zc + meas[3][1] * xc + meas[3][2] * yc;
        }
        e0 += __shfl_xor_sync(FULL, e0, 1);
        e1 += __shfl_xor_sync(FULL, e1, 1);
        e2 += __shfl_xor_sync(FULL, e2, 1);
        e3 += __shfl_xor_sync(FULL, e3, 1);
        e0 += __shfl_xor_sync(FULL, e0, 2);
        e1 += __shfl_xor_sync(FULL, e1, 2);
        e2 += __shfl_xor_sync(FULL, e2, 2);
        e3 += __shfl_xor_sync(FULL, e3, 2);

        if (s == 0 && t < 784)
            feat4[p] = make_float4(e0, e1, e2, e3);
    }

    // ---- 4. wait for weight prefetch + feat visibility ----
    asm volatile("cp.async.wait_group 0;\n" ::: "memory");
    __syncthreads();

    // ---- 5. fc1: warps 0..15, 4 neurons each, everything from smem ----
    if (warp < 16) {
        int n0 = warp * 4;
        const float4* fv  = feat4;
        const float4* wv0 = reinterpret_cast<const float4*>(w1s + (n0 + 0) * NFEAT);
        const float4* wv1 = reinterpret_cast<const float4*>(w1s + (n0 + 1) * NFEAT);
        const float4* wv2 = reinterpret_cast<const float4*>(w1s + (n0 + 2) * NFEAT);
        const float4* wv3 = reinterpret_cast<const float4*>(w1s + (n0 + 3) * NFEAT);

        float a0 = 0.f, a1 = 0.f, a2 = 0.f, a3 = 0.f;
        if (lane < 28) {
#pragma unroll
            for (int j = 0; j < 7; j++) {
                int k = j * 28 + lane;
                float4 fa = fv[k];
                float4 w0 = wv0[k], w1v = wv1[k], w2v = wv2[k], w3v = wv3[k];
                a0 = fmaf(fa.x, w0.x,  fmaf(fa.y, w0.y,  fmaf(fa.z, w0.z,  fmaf(fa.w, w0.w,  a0))));
                a1 = fmaf(fa.x, w1v.x, fmaf(fa.y, w1v.y, fmaf(fa.z, w1v.z, fmaf(fa.w, w1v.w, a1))));
                a2 = fmaf(fa.x, w2v.x, fmaf(fa.y, w2v.y, fmaf(fa.z, w2v.z, fmaf(fa.w, w2v.w, a2))));
                a3 = fmaf(fa.x, w3v.x, fmaf(fa.y, w3v.y, fmaf(fa.z, w3v.z, fmaf(fa.w, w3v.w, a3))));
            }
        }
#pragma unroll
        for (int off = 16; off > 0; off >>= 1) {
            a0 += __shfl_xor_sync(FULL, a0, off);
            a1 += __shfl_xor_sync(FULL, a1, off);
            a2 += __shfl_xor_sync(FULL, a2, off);
            a3 += __shfl_xor_sync(FULL, a3, off);
        }
        if (lane == 0) {
            hids[n0 + 0] = fmaxf(a0 + b1s[n0 + 0], 0.f);
            hids[n0 + 1] = fmaxf(a1 + b1s[n0 + 1], 0.f);
            hids[n0 + 2] = fmaxf(a2 + b1s[n0 + 2], 0.f);
            hids[n0 + 3] = fmaxf(a3 + b1s[n0 + 3], 0.f);
        }
    }
    __syncthreads();

    // ---- 6. fc2: warps 0..9, one output each ----
    if (warp < 10) {
        float acc = 0.f;
        if (lane < 16) {
            float4 h  = reinterpret_cast<const float4*>(hids)[lane];
            float4 ww = reinterpret_cast<const float4*>(w2s + warp * NHID)[lane];
            acc = h.x * ww.x + h.y * ww.y + h.z * ww.z + h.w * ww.w;
        }
#pragma unroll
        for (int off = 8; off > 0; off >>= 1)
            acc += __shfl_xor_sync(FULL, acc, off);
        if (lane == 0)
            out[b * 10 + warp] = acc + b2[warp];
    }
}

extern "C" void kernel_launch(void* const* d_in, const int* in_sizes, int n_in,
                              void* d_out, int out_size) {
    const float* x     = (const float*)d_in[0];
    const float* w     = (const float*)d_in[1];
    const float* fc1_w = (const float*)d_in[2];
    const float* fc1_b = (const float*)d_in[3];
    const float* fc2_w = (const float*)d_in[4];
    const float* fc2_b = (const float*)d_in[5];
    float* out = (float*)d_out;

    cudaFuncSetAttribute(fused_kernel,
                         cudaFuncAttributeMaxDynamicSharedMemorySize, SMEM_TOTAL);
    fused_kernel<<<BATCH, 832, SMEM_TOTAL>>>(x, w, fc1_w, fc1_b, fc2_w, fc2_b, out);
}

// round 10
// speedup vs baseline: 1.8547x; 1.0239x over previous
#include <cuda_runtime.h>
#include <math_constants.h>

#define LPATCH  (14*14)
#define BATCH   128
#define NFEAT   784
#define NHID    64

// Dynamic smem layout (bytes)
#define FEAT_OFF 0               // 196 float4 = 3136 B
#define W1_OFF   3136            // 64*784 floats = 200704 B
#define W2_OFF   203840          // 10*64 floats = 2560 B
#define B1_OFF   206400          // 64 floats = 256 B
#define HID_OFF  206656          // 64 floats = 256 B
#define SMEM_TOTAL 206912

__device__ __forceinline__ void cp_async16(void* sptr, const void* gptr) {
    unsigned s = (unsigned)__cvta_generic_to_shared(sptr);
    asm volatile("cp.async.cg.shared.global [%0], [%1], 16;\n" :: "r"(s), "l"(gptr));
}

// result = co*own + cp*partner (complex MAC, co=(cox,coy), cp=(cpx,cpy))
#define CMAC(nx, ny, cox, coy, cpx, cpy, ox, oy, qx, qy)             \
    nx = (cox)*(ox) - (coy)*(oy) + (cpx)*(qx) - (cpy)*(qy);          \
    ny = (cox)*(oy) + (coy)*(ox) + (cpx)*(qy) + (cpy)*(qx);

// Full complex 2x2 on an in-register amplitude pair
#define LOCAL_GATE(u, lox, loy, hix, hiy) do {                        \
    float _lx = (u).x*(lox) + (u).y*(loy) - (u).z*(hix) - (u).w*(hiy);\
    float _ly = (u).x*(loy) - (u).y*(lox) - (u).z*(hiy) + (u).w*(hix);\
    float _hx = (u).z*(lox) - (u).w*(loy) + (u).x*(hix) - (u).y*(hiy);\
    float _hy = (u).z*(loy) + (u).w*(lox) + (u).x*(hiy) + (u).y*(hix);\
    (lox)=_lx; (loy)=_ly; (hix)=_hx; (hiy)=_hy;                       \
} while (0)

// inverse of the CNOT-ring basis permutation, packed as nibbles (j -> sigma^-1(j))
#define SIGMA_INV_PACKED 0x497A2F1C85B6E3D0ull

// One block per batch row: 832 threads.
//   threads 0..799 : circuit, 4 threads per patch (196 patches), feat -> smem
//   all threads    : cp.async prefetch of w1/w2/b1 into smem (hidden behind circuit)
//   warps 0..15    : fc1 (4 neurons each) from smem;  warps 0..9 : fc2 -> out
__global__ void __launch_bounds__(832, 1) fused_kernel(
    const float* __restrict__ x,      // [128,1,28,28]
    const float* __restrict__ w,      // [60]
    const float* __restrict__ w1,     // [64,784]
    const float* __restrict__ b1,     // [64]
    const float* __restrict__ w2,     // [10,64]
    const float* __restrict__ b2,     // [10]
    float* __restrict__ out)          // [128,10]
{
    extern __shared__ char smem_raw[];
    float4* feat4 = reinterpret_cast<float4*>(smem_raw + FEAT_OFF);
    float*  w1s   = reinterpret_cast<float*>(smem_raw + W1_OFF);
    float*  w2s   = reinterpret_cast<float*>(smem_raw + W2_OFF);
    float*  b1s   = reinterpret_cast<float*>(smem_raw + B1_OFF);
    float*  hids  = reinterpret_cast<float*>(smem_raw + HID_OFF);

    __shared__ float4 um[16];         // fused yzy, layers 0..3 x qubits 0..3
    __shared__ float  meas[4][3];     // nz,nx,ny per qubit (layer 4 folded)

    const int t = threadIdx.x;
    const int b = blockIdx.x;

    // ---- 1. fire-and-forget prefetch of MLP weights into smem ----
    for (int i = t; i < (NHID * NFEAT) / 4; i += 832)
        cp_async16(w1s + i * 4, w1 + i * 4);
    if (t < 160) cp_async16(w2s + t * 4, w2 + t * 4);
    if (t < 16)  cp_async16(b1s + t * 4, b1 + t * 4);
    asm volatile("cp.async.commit_group;\n" ::: "memory");

    // ---- 2. gate-constant setup ----
    if (t < 16) {
        int l = t >> 2, q = t & 3;
        float a = w[l * 12 + q], bb = w[l * 12 + 4 + q], c = w[l * 12 + 8 + q];
        float sP, cP, sQ, cQ, sB, cB;
        sincosf(0.5f * (a + c), &sP, &cP);
        sincosf(0.5f * (a - c), &sQ, &cQ);
        sincosf(0.5f * bb,      &sB, &cB);
        um[t] = make_float4(cB * cP, sB * cQ, cB * sP, sB * sQ);
    } else if (t < 20) {
        int q = t - 16;
        float a = w[48 + q], bb = w[48 + 4 + q], c = w[48 + 8 + q];
        float sa, ca, sb, cb, sc, cc;
        sincosf(a, &sa, &ca);
        sincosf(bb, &sb, &cb);
        sincosf(c, &sc, &cc);
        meas[q][0] =  cc * ca - sc * cb * sa;   // nz
        meas[q][1] = -cc * sa - sc * cb * ca;   // nx
        meas[q][2] =  sc * sb;                  // ny
    }
    __syncthreads();

    const unsigned FULL = 0xffffffffu;
    const int lane = t & 31;
    const int warp = t >> 5;

    // ---- 3. circuit ----
    if (t < 800) {
        int p = t >> 2;
        if (p > 195) p = 195;           // dummy lanes in warp 24 (no write)
        const int s = t & 3;
        const int pi = p / 14, pj = p - pi * 14;

        const float* xb = x + b * 784 + (2 * pi) * 28 + 2 * pj;
        float xpix = xb[(s >> 1) * 28 + (s & 1)];
        float hs_l, hc_l;
        __sincosf(CUDART_PI_F * xpix, &hs_l, &hc_l);

        int base = lane & ~3;
        float hcq[4], hsq[4];
#pragma unroll
        for (int q = 0; q < 4; q++) {
            hcq[q] = __shfl_sync(FULL, hc_l, base + q);
            hsq[q] = __shfl_sync(FULL, hs_l, base + q);
        }

        // ---- init: layer 0 folded into per-qubit vectors, ring 0 folded as
        //      basis permutation sigma. v_q = U0_q * Rx(theta_q)|0>.
        float v0lx, v0ly, v0hx, v0hy, v1lx, v1ly, v1hx, v1hy;
        float v2lx, v2ly, v2hx, v2hy, v3lx, v3ly, v3hx, v3hy;
        {
            float4 u;
            u = um[0];
            v0lx = hcq[0]*u.x + hsq[0]*u.w;  v0ly = -hcq[0]*u.y + hsq[0]*u.z;
            v0hx = hcq[0]*u.z + hsq[0]*u.y;  v0hy =  hcq[0]*u.w - hsq[0]*u.x;
            u = um[1];
            v1lx = hcq[1]*u.x + hsq[1]*u.w;  v1ly = -hcq[1]*u.y + hsq[1]*u.z;
            v1hx = hcq[1]*u.z + hsq[1]*u.y;  v1hy =  hcq[1]*u.w - hsq[1]*u.x;
            u = um[2];
            v2lx = hcq[2]*u.x + hsq[2]*u.w;  v2ly = -hcq[2]*u.y + hsq[2]*u.z;
            v2hx = hcq[2]*u.z + hsq[2]*u.y;  v2hy =  hcq[2]*u.w - hsq[2]*u.x;
            u = um[3];
            v3lx = hcq[3]*u.x + hsq[3]*u.w;  v3ly = -hcq[3]*u.y + hsq[3]*u.z;
            v3hx = hcq[3]*u.z + hsq[3]*u.y;  v3hy =  hcq[3]*u.w - hsq[3]*u.x;
        }

        float ax[4], ay[4];
#pragma unroll
        for (int r = 0; r < 4; r++) {
            int j = (s << 2) | r;
            int i = (int)((SIGMA_INV_PACKED >> (4 * j)) & 15ull);
            float w0x = (i & 8) ? v0hx : v0lx,  w0y = (i & 8) ? v0hy : v0ly;
            float w1x = (i & 4) ? v1hx : v1lx,  w1y = (i & 4) ? v1hy : v1ly;
            float w2x = (i & 2) ? v2hx : v2lx,  w2y = (i & 2) ? v2hy : v2ly;
            float w3x = (i & 1) ? v3hx : v3lx,  w3y = (i & 1) ? v3hy : v3ly;
            float tx = w0x * w1x - w0y * w1y;
            float ty = w0x * w1y + w0y * w1x;
            float ux_ = tx * w2x - ty * w2y;
            float uy_ = tx * w2y + ty * w2x;
            ax[r] = ux_ * w3x - uy_ * w3y;
            ay[r] = ux_ * w3y + uy_ * w3x;
        }

        // ---- layers 1..3 ----
#pragma unroll
        for (int l = 1; l <= 3; l++) {
            // gate q0 (thread bit 2); layers 2,3 fold previous ring's CNOT(q3->q0):
            //   operand swap (own<->partner) for r with q3 bit set (r&1)
            {
                float4 u = um[l * 4 + 0];
                float coy = (s & 2) ? u.y : -u.y;
                float cpx = (s & 2) ? u.z : -u.z;
                const bool fold30 = (l >= 2);
#pragma unroll
                for (int r = 0; r < 4; r++) {
                    float qx = __shfl_xor_sync(FULL, ax[r], 2);
                    float qy = __shfl_xor_sync(FULL, ay[r], 2);
                    float nx_, ny_;
                    if (fold30 && (r & 1)) {
                        CMAC(nx_, ny_, cpx, u.w, u.x, coy, ax[r], ay[r], qx, qy);
                    } else {
                        CMAC(nx_, ny_, u.x, coy, cpx, u.w, ax[r], ay[r], qx, qy);
                    }
                    ax[r] = nx_; ay[r] = ny_;
                }
            }
            // gate q1 (thread bit 1) with same-layer CNOT(q0->q1) folded:
            //   row = bt ^ ctrl; own/partner coeffs swap when ctrl set
            {
                float4 u = um[l * 4 + 1];
                bool ctrl = (s & 2) != 0;
                bool row  = (((s & 1) != 0) != ctrl);
                float dy = row ? u.y : -u.y;
                float oz = row ? u.z : -u.z;
                float cox = ctrl ? oz  : u.x;
                float coy = ctrl ? u.w : dy;
                float cpx = ctrl ? u.x : oz;
                float cpy = ctrl ? dy  : u.w;
#pragma unroll
                for (int r = 0; r < 4; r++) {
                    float qx = __shfl_xor_sync(FULL, ax[r], 1);
                    float qy = __shfl_xor_sync(FULL, ay[r], 1);
                    float nx_, ny_;
                    CMAC(nx_, ny_, cox, coy, cpx, cpy, ax[r], ay[r], qx, qy);
                    ax[r] = nx_; ay[r] = ny_;
                }
            }
            // gates q2, q3 (local register butterflies)
            {
                float4 u2 = um[l * 4 + 2];
                LOCAL_GATE(u2, ax[0], ay[0], ax[2], ay[2]);
                LOCAL_GATE(u2, ax[1], ay[1], ax[3], ay[3]);
                float4 u3 = um[l * 4 + 3];
                LOCAL_GATE(u3, ax[0], ay[0], ax[1], ay[1]);
                LOCAL_GATE(u3, ax[2], ay[2], ax[3], ay[3]);
            }
            // ring: C(q0->q1) folded above; C(q1->q2) explicit; C(q2->q3) swap;
            //       C(q3->q0) deferred to next layer's q0 gate (explicit after l=3)
            if (s & 1) {
                float tx;
                tx = ax[0]; ax[0] = ax[2]; ax[2] = tx;
                tx = ay[0]; ay[0] = ay[2]; ay[2] = tx;
                tx = ax[1]; ax[1] = ax[3]; ax[3] = tx;
                tx = ay[1]; ay[1] = ay[3]; ay[3] = tx;
            }
            {
                float tx;
                tx = ax[2]; ax[2] = ax[3]; ax[3] = tx;
                tx = ay[2]; ay[2] = ay[3]; ay[3] = tx;
            }
            if (l == 3) {   // last ring's C(q3->q0): explicit
                ax[1] = __shfl_xor_sync(FULL, ax[1], 2);
                ay[1] = __shfl_xor_sync(FULL, ay[1], 2);
                ax[3] = __shfl_xor_sync(FULL, ax[3], 2);
                ay[3] = __shfl_xor_sync(FULL, ay[3], 2);
            }
        }

        // ---- layer-4-folded measurement: e_q = nz*<Z> + nx*<X> + ny*<Y> ----
        float pr[4];
#pragma unroll
        for (int r = 0; r < 4; r++) pr[r] = ax[r] * ax[r] + ay[r] * ay[r];

        float e0, e1, e2, e3;
        {   // q0 (cross, mask 2)
            float zc = 0.f, xc = 0.f, yc = 0.f;
#pragma unroll
            for (int r = 0; r < 4; r++) {
                float qx = __shfl_xor_sync(FULL, ax[r], 2);
                float qy = __shfl_xor_sync(FULL, ay[r], 2);
                zc += pr[r];
                xc += ax[r] * qx + ay[r] * qy;
                yc += ax[r] * qy - ay[r] * qx;
            }
            if (s & 2) { zc = -zc; yc = -yc; }
            e0 = meas[0][0] * zc + meas[0][1] * xc + meas[0][2] * yc;
        }
        {   // q1 (cross, mask 1)
            float zc = 0.f, xc = 0.f, yc = 0.f;
#pragma unroll
            for (int r = 0; r < 4; r++) {
                float qx = __shfl_xor_sync(FULL, ax[r], 1);
                float qy = __shfl_xor_sync(FULL, ay[r], 1);
                zc += pr[r];
                xc += ax[r] * qx + ay[r] * qy;
                yc += ax[r] * qy - ay[r] * qx;
            }
            if (s & 1) { zc = -zc; yc = -yc; }
            e1 = meas[1][0] * zc + meas[1][1] * xc + meas[1][2] * yc;
        }
        {   // q2 (local)
            float zc = pr[0] + pr[1] - pr[2] - pr[3];
            float xc = 2.f * (ax[0]*ax[2] + ay[0]*ay[2] + ax[1]*ax[3] + ay[1]*ay[3]);
            float yc = 2.f * (ax[0]*ay[2] - ay[0]*ax[2] + ax[1]*ay[3] - ay[1]*ax[3]);
            e2 = meas[2][0] * zc + meas[2][1] * xc + meas[2][2] * yc;
        }
        {   // q3 (local)
            float zc = pr[0] - pr[1] + pr[2] - pr[3];
            float xc = 2.f * (ax[0]*ax[1] + ay[0]*ay[1] + ax[2]*ax[3] + ay[2]*ay[3]);
            float yc = 2.f * (ax[0]*ay[1] - ay[0]*ax[1] + ax[2]*ay[3] - ay[2]*ax[3]);
            e3 = meas[3][0] * zc + meas[3][1] * xc + meas[3][2] * yc;
        }
        e0 += __shfl_xor_sync(FULL, e0, 1);
        e1 += __shfl_xor_sync(FULL, e1, 1);
        e2 += __shfl_xor_sync(FULL, e2, 1);
        e3 += __shfl_xor_sync(FULL, e3, 1);
        e0 += __shfl_xor_sync(FULL, e0, 2);
        e1 += __shfl_xor_sync(FULL, e1, 2);
        e2 += __shfl_xor_sync(FULL, e2, 2);
        e3 += __shfl_xor_sync(FULL, e3, 2);

        if (s == 0 && t < 784)
            feat4[p] = make_float4(e0, e1, e2, e3);
    }

    // ---- 4. wait for weight prefetch + feat visibility ----
    asm volatile("cp.async.wait_group 0;\n" ::: "memory");
    __syncthreads();

    // ---- 5. fc1: warps 0..15, 4 neurons each, everything from smem ----
    if (warp < 16) {
        int n0 = warp * 4;
        const float4* fv  = feat4;
        const float4* wv0 = reinterpret_cast<const float4*>(w1s + (n0 + 0) * NFEAT);
        const float4* wv1 = reinterpret_cast<const float4*>(w1s + (n0 + 1) * NFEAT);
        const float4* wv2 = reinterpret_cast<const float4*>(w1s + (n0 + 2) * NFEAT);
        const float4* wv3 = reinterpret_cast<const float4*>(w1s + (n0 + 3) * NFEAT);

        float a0 = 0.f, a1 = 0.f, a2 = 0.f, a3 = 0.f;
        if (lane < 28) {
#pragma unroll
            for (int j = 0; j < 7; j++) {
                int k = j * 28 + lane;
                float4 fa = fv[k];
                float4 w0 = wv0[k], w1v = wv1[k], w2v = wv2[k], w3v = wv3[k];
                a0 = fmaf(fa.x, w0.x,  fmaf(fa.y, w0.y,  fmaf(fa.z, w0.z,  fmaf(fa.w, w0.w,  a0))));
                a1 = fmaf(fa.x, w1v.x, fmaf(fa.y, w1v.y, fmaf(fa.z, w1v.z, fmaf(fa.w, w1v.w, a1))));
                a2 = fmaf(fa.x, w2v.x, fmaf(fa.y, w2v.y, fmaf(fa.z, w2v.z, fmaf(fa.w, w2v.w, a2))));
                a3 = fmaf(fa.x, w3v.x, fmaf(fa.y, w3v.y, fmaf(fa.z, w3v.z, fmaf(fa.w, w3v.w, a3))));
            }
        }
#pragma unroll
        for (int off = 16; off > 0; off >>= 1) {
            a0 += __shfl_xor_sync(FULL, a0, off);
            a1 += __shfl_xor_sync(FULL, a1, off);
            a2 += __shfl_xor_sync(FULL, a2, off);
            a3 += __shfl_xor_sync(FULL, a3, off);
        }
        if (lane == 0) {
            hids[n0 + 0] = fmaxf(a0 + b1s[n0 + 0], 0.f);
            hids[n0 + 1] = fmaxf(a1 + b1s[n0 + 1], 0.f);
            hids[n0 + 2] = fmaxf(a2 + b1s[n0 + 2], 0.f);
            hids[n0 + 3] = fmaxf(a3 + b1s[n0 + 3], 0.f);
        }
    }
    __syncthreads();

    // ---- 6. fc2: warps 0..9, one output each ----
    if (warp < 10) {
        float acc = 0.f;
        if (lane < 16) {
            float4 h  = reinterpret_cast<const float4*>(hids)[lane];
            float4 ww = reinterpret_cast<const float4*>(w2s + warp * NHID)[lane];
            acc = h.x * ww.x + h.y * ww.y + h.z * ww.z + h.w * ww.w;
        }
#pragma unroll
        for (int off = 8; off > 0; off >>= 1)
            acc += __shfl_xor_sync(FULL, acc, off);
        if (lane == 0)
            out[b * 10 + warp] = acc + b2[warp];
    }
}

extern "C" void kernel_launch(void* const* d_in, const int* in_sizes, int n_in,
                              void* d_out, int out_size) {
    const float* x     = (const float*)d_in[0];
    const float* w     = (const float*)d_in[1];
    const float* fc1_w = (const float*)d_in[2];
    const float* fc1_b = (const float*)d_in[3];
    const float* fc2_w = (const float*)d_in[4];
    const float* fc2_b = (const float*)d_in[5];
    float* out = (float*)d_out;

    cudaFuncSetAttribute(fused_kernel,
                         cudaFuncAttributeMaxDynamicSharedMemorySize, SMEM_TOTAL);
    fused_kernel<<<BATCH, 832, SMEM_TOTAL>>>(x, w, fc1_w, fc1_b, fc2_w, fc2_b, out);
}